// round 1
// baseline (speedup 1.0000x reference)
#include <cuda_runtime.h>
#include <cstdint>

// Problem constants
#define NPTS      65536      // 16*64*64 spatial positions
#define DIM       64
#define NCODE     1024
#define HW        4096       // 64*64
#define CHW       262144     // 64*64*64
#define TOTAL_Q   4194304    // 16*64*64*64

// Output layout (concatenated, reference return order, float32)
#define OFF_Q     0
#define OFF_LOSS  4194304
#define OFF_IDX   4194305
#define OFF_EMB   4259841
#define OFF_CS    4325377
#define OFF_EA    4326401

// Scratch (device globals; no allocation allowed)
__device__ float g_dw[DIM * NCODE];
__device__ float g_enc[NCODE];
__device__ float g_e2[NCODE];
__device__ float g_loss;

// ---------------------------------------------------------------------------
// Kernel 1: zero scratch + compute e2[k] = sum_d E[d][k]^2
// ---------------------------------------------------------------------------
__global__ void vq_init(const float* __restrict__ E) {
    int i = blockIdx.x * blockDim.x + threadIdx.x;
    if (i < DIM * NCODE) g_dw[i] = 0.0f;
    if (i < NCODE) {
        g_enc[i] = 0.0f;
        float s = 0.0f;
#pragma unroll
        for (int d = 0; d < DIM; ++d) {
            float v = E[d * NCODE + i];
            s = fmaf(v, v, s);
        }
        g_e2[i] = s;
    }
    if (i == 0) g_loss = 0.0f;
}

// ---------------------------------------------------------------------------
// Kernel 2: fused distance GEMM + argmin + quantize + loss + EMA atomics
// Block: 256 threads, 128 points. Loops over 8 chunks of 128 codes.
// Micro-tile: 8 points x 8 codes per thread (16x16 thread grid).
// ---------------------------------------------------------------------------
__global__ void __launch_bounds__(256, 2)
vq_main(const float* __restrict__ x, const float* __restrict__ E,
        float* __restrict__ out) {
    extern __shared__ float sm[];
    float* x_s     = sm;                 // [64][128]
    float* e_s     = sm + 8192;          // [64][128]
    float* run_val = sm + 16384;         // [128]
    int*   run_idx = (int*)(sm + 16512); // [128]
    float* red     = sm + 16640;         // [256]

    const int tid = threadIdx.x;
    const int n0 = blockIdx.x * 128;
    const int bimg = n0 >> 12;           // n0 / 4096
    const int p0 = n0 & 4095;
    const float* xb = x + (size_t)bimg * CHW + p0;

    // Load x tile: x_s[c][m] = x[b][c][.][.] for 128 consecutive points
#pragma unroll
    for (int r = 0; r < 8; ++r) {
        int f = tid + 256 * r;           // 0..2047 float4s
        int c = f >> 5;
        int q = f & 31;
        float4 v = *(const float4*)(xb + c * HW + q * 4);
        *(float4*)(x_s + c * 128 + q * 4) = v;
    }
    if (tid < 128) {
        run_val[tid] = 3.4e38f;
        run_idx[tid] = 0;
    }
    __syncthreads();

    const int tx = tid & 15;
    const int ty = tid >> 4;

    for (int chunk = 0; chunk < 8; ++chunk) {
        if (chunk) __syncthreads();  // protect e_s reuse
        // Load E chunk: e_s[d][j] = E[d][chunk*128 + j]
#pragma unroll
        for (int r = 0; r < 8; ++r) {
            int f = tid + 256 * r;
            int d = f >> 5;
            int q = f & 31;
            float4 v = *(const float4*)(E + d * NCODE + chunk * 128 + q * 4);
            *(float4*)(e_s + d * 128 + q * 4) = v;
        }
        __syncthreads();

        float acc[8][8];
#pragma unroll
        for (int i = 0; i < 8; ++i)
#pragma unroll
            for (int j = 0; j < 8; ++j) acc[i][j] = 0.0f;

#pragma unroll 4
        for (int c = 0; c < 64; ++c) {
            float4 a0 = *(const float4*)(x_s + c * 128 + ty * 8);
            float4 a1 = *(const float4*)(x_s + c * 128 + ty * 8 + 4);
            float4 b0 = *(const float4*)(e_s + c * 128 + tx * 8);
            float4 b1 = *(const float4*)(e_s + c * 128 + tx * 8 + 4);
            float a[8] = {a0.x, a0.y, a0.z, a0.w, a1.x, a1.y, a1.z, a1.w};
            float b[8] = {b0.x, b0.y, b0.z, b0.w, b1.x, b1.y, b1.z, b1.w};
#pragma unroll
            for (int i = 0; i < 8; ++i)
#pragma unroll
                for (int j = 0; j < 8; ++j)
                    acc[i][j] = fmaf(a[i], b[j], acc[i][j]);
        }

        // scores s = e2[k] - 2*dot; per-thread min over its 8 codes
        const int kbase = chunk * 128 + tx * 8;
        float e2v[8];
#pragma unroll
        for (int j = 0; j < 8; ++j) e2v[j] = g_e2[kbase + j];

#pragma unroll
        for (int i = 0; i < 8; ++i) {
            float bv = 3.4e38f;
            int bi = 0;
#pragma unroll
            for (int j = 0; j < 8; ++j) {
                float s = fmaf(-2.0f, acc[i][j], e2v[j]);
                if (s < bv) { bv = s; bi = kbase + j; }
            }
            // reduce across the 16 tx lanes (same ty)
#pragma unroll
            for (int off = 8; off > 0; off >>= 1) {
                float ov = __shfl_xor_sync(0xffffffffu, bv, off);
                int   oi = __shfl_xor_sync(0xffffffffu, bi, off);
                if (ov < bv || (ov == bv && oi < bi)) { bv = ov; bi = oi; }
            }
            if (tx == 0) {
                int m = ty * 8 + i;
                if (bv < run_val[m]) { run_val[m] = bv; run_idx[m] = bi; }
            }
        }
    }
    __syncthreads();

    // ---- epilogue ----
    if (tid < 128) {
        int k = run_idx[tid];
        out[OFF_IDX + n0 + tid] = (float)k;
        atomicAdd(&g_enc[k], 1.0f);
    }

    float lsum = 0.0f;
    float* outq = out + OFF_Q + (size_t)bimg * CHW + p0;
#pragma unroll 4
    for (int r = 0; r < 32; ++r) {
        int e = tid + 256 * r;           // 0..8191
        int c = e >> 7;
        int m = e & 127;
        int k = run_idx[m];
        float xv = x_s[c * 128 + m];
        float ev = E[c * NCODE + k];
        float diff = ev - xv;
        outq[c * HW + m] = xv + diff;    // mimic inputs + (quantized - inputs)
        lsum = fmaf(diff, diff, lsum);
        atomicAdd(&g_dw[c * NCODE + k], xv);
    }

    red[tid] = lsum;
    __syncthreads();
    for (int s = 128; s > 0; s >>= 1) {
        if (tid < s) red[tid] += red[tid + s];
        __syncthreads();
    }
    if (tid == 0) atomicAdd(&g_loss, red[0]);
}

// ---------------------------------------------------------------------------
// Kernel 3: EMA finalize + loss scalar
// ---------------------------------------------------------------------------
__global__ void vq_fin(const float* __restrict__ cs_in,
                       const float* __restrict__ ea_in,
                       float* __restrict__ out) {
    __shared__ float red[1024];
    int k = threadIdx.x;
    float ncs = cs_in[k] * 0.99f + 0.01f * g_enc[k];
    red[k] = ncs;
    __syncthreads();
    for (int s = 512; s > 0; s >>= 1) {
        if (k < s) red[k] += red[k + s];
        __syncthreads();
    }
    float n = red[0];
    out[OFF_CS + k] = ncs;
    float cs = (ncs + 1e-5f) / (n + 1024.0f * 1e-5f) * n;
#pragma unroll
    for (int d = 0; d < DIM; ++d) {
        int idx = d * NCODE + k;
        float nea = ea_in[idx] * 0.99f + 0.01f * g_dw[idx];
        out[OFF_EA + idx] = nea;
        out[OFF_EMB + idx] = nea / cs;
    }
    if (k == 0) out[OFF_LOSS] = 0.25f * g_loss * (1.0f / (float)TOTAL_Q);
}

// ---------------------------------------------------------------------------
extern "C" void kernel_launch(void* const* d_in, const int* in_sizes, int n_in,
                              void* d_out, int out_size) {
    const float* x  = (const float*)d_in[0];  // inputs [16,64,64,64]
    const float* E  = (const float*)d_in[1];  // embedding [64,1024]
    const float* cs = (const float*)d_in[2];  // cluster_size [1024]
    const float* ea = (const float*)d_in[3];  // embed_avg [64,1024]
    float* out = (float*)d_out;

    const int smem = 16896 * 4;  // 67584 bytes
    cudaFuncSetAttribute(vq_main, cudaFuncAttributeMaxDynamicSharedMemorySize, smem);

    vq_init<<<256, 256>>>(E);
    vq_main<<<NPTS / 128, 256, smem>>>(x, E, out);
    vq_fin<<<1, 1024>>>(cs, ea, out);
}